// round 5
// baseline (speedup 1.0000x reference)
#include <cuda_runtime.h>
#include <cstdint>

#define N_MAX   50000
#define HDIM    256
#define E_MAX   800000
#define MAXCTX  8

// ---------------------------------------------------------------------------
// Scratch (device globals -- no allocation allowed in kernel_launch)
// ---------------------------------------------------------------------------
__device__ float g_h[N_MAX * HDIM];     // h = A @ W
__device__ float g_agg[N_MAX * HDIM];   // scatter accumulator
__device__ float g_feat[N_MAX * HDIM];  // layer output (feat1 then feat2)
__device__ float g_inv[N_MAX];          // deg, then rsqrt(deg)

// ---------------------------------------------------------------------------
// Degree / normalization
// ---------------------------------------------------------------------------
__global__ void deg_init_kernel(float* deg, int n) {
    int i = blockIdx.x * blockDim.x + threadIdx.x;
    if (i < n) deg[i] = 1.0f;  // self loop
}

__global__ void deg_count_kernel(const int* __restrict__ dst, float* deg, int e) {
    int i = blockIdx.x * blockDim.x + threadIdx.x;
    if (i < e) atomicAdd(&deg[dst[i]], 1.0f);
}

__global__ void inv_sqrt_kernel(float* deg, int n) {
    int i = blockIdx.x * blockDim.x + threadIdx.x;
    if (i < n) deg[i] = rsqrtf(deg[i]);   // deg >= 1 always
}

// ---------------------------------------------------------------------------
// SGEMM: C[M,256] = A[M,256] @ B[256,256]
// BM=128, BN=128, BK=16, 256 threads, 8x8 per thread
// ---------------------------------------------------------------------------
__global__ __launch_bounds__(256) void sgemm_kernel(
    const float* __restrict__ A, const float* __restrict__ B,
    float* __restrict__ C, int M)
{
    const int K = 256;
    __shared__ float As[16][128];   // transposed: As[k][m]
    __shared__ float Bs[16][128];

    const int block_row = blockIdx.x * 128;
    const int block_col = blockIdx.y * 128;
    const int tid = threadIdx.x;
    const int tr = tid >> 4;            // 0..15
    const int tc = tid & 15;            // 0..15

    const int a_row0 = tid >> 2;        // 0..63
    const int a_col  = (tid & 3) * 4;   // 0,4,8,12
    const int b_row0 = tid >> 5;        // 0..7
    const int b_col  = (tid & 31) * 4;  // 0..124

    float acc[8][8] = {};

    for (int k0 = 0; k0 < K; k0 += 16) {
        #pragma unroll
        for (int it = 0; it < 2; ++it) {
            int m = a_row0 + it * 64;
            int gr = block_row + m;
            float4 v = make_float4(0.f, 0.f, 0.f, 0.f);
            if (gr < M) v = *(const float4*)(A + (size_t)gr * K + k0 + a_col);
            As[a_col + 0][m] = v.x;
            As[a_col + 1][m] = v.y;
            As[a_col + 2][m] = v.z;
            As[a_col + 3][m] = v.w;
        }
        #pragma unroll
        for (int it = 0; it < 2; ++it) {
            int kk = b_row0 + it * 8;
            *(float4*)&Bs[kk][b_col] =
                *(const float4*)(B + (size_t)(k0 + kk) * 256 + block_col + b_col);
        }
        __syncthreads();

        #pragma unroll
        for (int kk = 0; kk < 16; ++kk) {
            float4 a0 = *(const float4*)&As[kk][tr * 8];
            float4 a1 = *(const float4*)&As[kk][tr * 8 + 4];
            float4 b0 = *(const float4*)&Bs[kk][tc * 8];
            float4 b1 = *(const float4*)&Bs[kk][tc * 8 + 4];
            float ar[8] = {a0.x, a0.y, a0.z, a0.w, a1.x, a1.y, a1.z, a1.w};
            float br[8] = {b0.x, b0.y, b0.z, b0.w, b1.x, b1.y, b1.z, b1.w};
            #pragma unroll
            for (int i = 0; i < 8; ++i)
                #pragma unroll
                for (int j = 0; j < 8; ++j)
                    acc[i][j] += ar[i] * br[j];
        }
        __syncthreads();
    }

    #pragma unroll
    for (int i = 0; i < 8; ++i) {
        int gr = block_row + tr * 8 + i;
        if (gr < M) {
            #pragma unroll
            for (int j = 0; j < 8; j += 4) {
                *(float4*)(C + (size_t)gr * 256 + block_col + tc * 8 + j) =
                    make_float4(acc[i][j], acc[i][j+1], acc[i][j+2], acc[i][j+3]);
            }
        }
    }
}

// ---------------------------------------------------------------------------
// Self-loop init: agg[v,:] = h[v,:] * inv[v]^2   (float4 granularity)
// ---------------------------------------------------------------------------
__global__ void selfinit_kernel(const float* __restrict__ h,
                                const float* __restrict__ inv,
                                float* __restrict__ agg, int total4)
{
    int t = blockIdx.x * blockDim.x + threadIdx.x;
    if (t >= total4) return;
    int row = t >> 6;   // 64 float4 per row
    float iv = inv[row]; iv *= iv;
    float4 v = ((const float4*)h)[t];
    v.x *= iv; v.y *= iv; v.z *= iv; v.w *= iv;
    ((float4*)agg)[t] = v;
}

// ---------------------------------------------------------------------------
// Edge scatter: agg[dst,:] += h[src,:] * inv[src]*inv[dst]
// One warp per edge, vectorized global reductions (red.global.add.v4.f32)
// ---------------------------------------------------------------------------
__global__ void scatter_kernel(const float* __restrict__ h,
                               const int* __restrict__ src,
                               const int* __restrict__ dst,
                               const float* __restrict__ inv,
                               float* __restrict__ agg, int e)
{
    int warp = (blockIdx.x * blockDim.x + threadIdx.x) >> 5;
    int lane = threadIdx.x & 31;
    if (warp >= e) return;
    int s = __ldg(&src[warp]);
    int d = __ldg(&dst[warp]);
    float coef = __ldg(&inv[s]) * __ldg(&inv[d]);
    const float4* hp = (const float4*)(h + (size_t)s * 256);
    float* ap = agg + (size_t)d * 256;
    #pragma unroll
    for (int it = 0; it < 2; ++it) {
        int idx = lane + it * 32;           // float4 index 0..63
        float4 v = hp[idx];
        v.x *= coef; v.y *= coef; v.z *= coef; v.w *= coef;
        asm volatile("red.global.add.v4.f32 [%0], {%1, %2, %3, %4};"
                     :: "l"(ap + (size_t)idx * 4),
                        "f"(v.x), "f"(v.y), "f"(v.z), "f"(v.w)
                     : "memory");
    }
}

// ---------------------------------------------------------------------------
// Epilogue: feat = (agg + b), optional relu     (float4 granularity)
// ---------------------------------------------------------------------------
template <bool RELU>
__global__ void epilogue_kernel(const float* __restrict__ agg,
                                const float* __restrict__ b,
                                float* __restrict__ feat, int total4)
{
    int t = blockIdx.x * blockDim.x + threadIdx.x;
    if (t >= total4) return;
    int c4 = t & 63;
    float4 v  = ((const float4*)agg)[t];
    float4 bb = ((const float4*)b)[c4];
    v.x += bb.x; v.y += bb.y; v.z += bb.z; v.w += bb.w;
    if (RELU) {
        v.x = fmaxf(v.x, 0.f); v.y = fmaxf(v.y, 0.f);
        v.z = fmaxf(v.z, 0.f); v.w = fmaxf(v.w, 0.f);
    }
    ((float4*)feat)[t] = v;
}

// ---------------------------------------------------------------------------
// Context GEMM, fused final:
//   out[i,c] = feat2[i,c] * ( sum_{j<len[i]} feat2[label[i,j],:] @ Wr[j*256:(j+1)*256, c]
//                             + rb[c] )
// Gathered-A SGEMM with K=2048, same 128x128x16 tiling.
// ---------------------------------------------------------------------------
__global__ __launch_bounds__(256) void ctx_gemm_kernel(
    const float* __restrict__ feat,
    const int* __restrict__ label,     // [M, 8]
    const int* __restrict__ clen,      // [M]
    const float* __restrict__ Wr,      // [2048, 256]
    const float* __restrict__ rb,      // [256]
    float* __restrict__ out, int M)
{
    const int K = 2048;
    __shared__ float As[16][128];
    __shared__ float Bs[16][128];
    __shared__ int   s_label[128][MAXCTX];
    __shared__ int   s_len[128];

    const int block_row = blockIdx.x * 128;
    const int block_col = blockIdx.y * 128;
    const int tid = threadIdx.x;
    const int tr = tid >> 4;
    const int tc = tid & 15;

    const int a_row0 = tid >> 2;
    const int a_col  = (tid & 3) * 4;
    const int b_row0 = tid >> 5;
    const int b_col  = (tid & 31) * 4;

    // Stage per-row metadata
    if (tid < 128) {
        int gr = block_row + tid;
        s_len[tid] = (gr < M) ? clen[gr] : 0;
    }
    for (int i = tid; i < 128 * MAXCTX; i += 256) {
        int r = i >> 3, j = i & 7;
        int gr = block_row + r;
        s_label[r][j] = (gr < M) ? label[(size_t)gr * MAXCTX + j] : 0;
    }
    __syncthreads();

    float acc[8][8] = {};

    for (int k0 = 0; k0 < K; k0 += 16) {
        #pragma unroll
        for (int it = 0; it < 2; ++it) {
            int m = a_row0 + it * 64;
            int k = k0 + a_col;
            int j = k >> 8, kc = k & 255;
            float4 v = make_float4(0.f, 0.f, 0.f, 0.f);
            if (j < s_len[m]) {
                v = *(const float4*)(feat + (size_t)s_label[m][j] * 256 + kc);
            }
            As[a_col + 0][m] = v.x;
            As[a_col + 1][m] = v.y;
            As[a_col + 2][m] = v.z;
            As[a_col + 3][m] = v.w;
        }
        #pragma unroll
        for (int it = 0; it < 2; ++it) {
            int kk = b_row0 + it * 8;
            *(float4*)&Bs[kk][b_col] =
                *(const float4*)(Wr + (size_t)(k0 + kk) * 256 + block_col + b_col);
        }
        __syncthreads();

        #pragma unroll
        for (int kk = 0; kk < 16; ++kk) {
            float4 a0 = *(const float4*)&As[kk][tr * 8];
            float4 a1 = *(const float4*)&As[kk][tr * 8 + 4];
            float4 b0 = *(const float4*)&Bs[kk][tc * 8];
            float4 b1 = *(const float4*)&Bs[kk][tc * 8 + 4];
            float ar[8] = {a0.x, a0.y, a0.z, a0.w, a1.x, a1.y, a1.z, a1.w};
            float br[8] = {b0.x, b0.y, b0.z, b0.w, b1.x, b1.y, b1.z, b1.w};
            #pragma unroll
            for (int i = 0; i < 8; ++i)
                #pragma unroll
                for (int j = 0; j < 8; ++j)
                    acc[i][j] += ar[i] * br[j];
        }
        __syncthreads();
    }

    // Fused epilogue: out = feat2 * (acc + rb)
    #pragma unroll
    for (int i = 0; i < 8; ++i) {
        int gr = block_row + tr * 8 + i;
        if (gr < M) {
            #pragma unroll
            for (int j = 0; j < 8; j += 4) {
                int col = block_col + tc * 8 + j;
                float4 bv = *(const float4*)(rb + col);
                float4 fv = *(const float4*)(feat + (size_t)gr * 256 + col);
                float4 o;
                o.x = (acc[i][j+0] + bv.x) * fv.x;
                o.y = (acc[i][j+1] + bv.y) * fv.y;
                o.z = (acc[i][j+2] + bv.z) * fv.z;
                o.w = (acc[i][j+3] + bv.w) * fv.w;
                *(float4*)(out + (size_t)gr * 256 + col) = o;
            }
        }
    }
}

// ---------------------------------------------------------------------------
// Launch
// ---------------------------------------------------------------------------
extern "C" void kernel_launch(void* const* d_in, const int* in_sizes, int n_in,
                              void* d_out, int out_size)
{
    const float* x     = (const float*)d_in[0];
    const int*   ei    = (const int*)  d_in[1];   // [2, E]: src row then dst row
    const int*   label = (const int*)  d_in[2];
    const int*   clen  = (const int*)  d_in[3];
    const float* gW    = (const float*)d_in[4];
    const float* gb    = (const float*)d_in[5];
    const float* rW    = (const float*)d_in[6];
    const float* rb    = (const float*)d_in[7];
    float*       out   = (float*)d_out;

    const int N = in_sizes[3];
    const int E = in_sizes[1] / 2;
    const int* src = ei;
    const int* dst = ei + E;

    float *h, *agg, *feat, *inv;
    cudaGetSymbolAddress((void**)&h,    g_h);
    cudaGetSymbolAddress((void**)&agg,  g_agg);
    cudaGetSymbolAddress((void**)&feat, g_feat);
    cudaGetSymbolAddress((void**)&inv,  g_inv);

    const int total4 = N * (HDIM / 4);           // float4 count of a feature buf
    const int TPB = 256;
    dim3 gemm_grid((N + 127) / 128, 2);

    // --- normalization ---
    deg_init_kernel<<<(N + TPB - 1) / TPB, TPB>>>(inv, N);
    deg_count_kernel<<<(E + TPB - 1) / TPB, TPB>>>(dst, inv, E);
    inv_sqrt_kernel<<<(N + TPB - 1) / TPB, TPB>>>(inv, N);

    // --- GCN layer 1: feat1 = relu(scatter(x@W) + b) ---
    sgemm_kernel<<<gemm_grid, TPB>>>(x, gW, h, N);
    selfinit_kernel<<<(total4 + TPB - 1) / TPB, TPB>>>(h, inv, agg, total4);
    scatter_kernel<<<(E * 32 + TPB - 1) / TPB, TPB>>>(h, src, dst, inv, agg, E);
    epilogue_kernel<true><<<(total4 + TPB - 1) / TPB, TPB>>>(agg, gb, feat, total4);

    // --- GCN layer 2: feat2 = scatter(feat1@W) + b ---
    sgemm_kernel<<<gemm_grid, TPB>>>(feat, gW, h, N);
    selfinit_kernel<<<(total4 + TPB - 1) / TPB, TPB>>>(h, inv, agg, total4);
    scatter_kernel<<<(E * 32 + TPB - 1) / TPB, TPB>>>(h, src, dst, inv, agg, E);
    epilogue_kernel<false><<<(total4 + TPB - 1) / TPB, TPB>>>(agg, gb, feat, total4);

    // --- context gather-GEMM fused with final elementwise product ---
    ctx_gemm_kernel<<<gemm_grid, TPB>>>(feat, label, clen, rW, rb, out, N);
}

// round 6
// speedup vs baseline: 1.4172x; 1.4172x over previous
#include <cuda_runtime.h>
#include <cstdint>

#define N_MAX   50000
#define HDIM    256
#define E_MAX   800000
#define MAXCTX  8

// ---------------------------------------------------------------------------
// Scratch (device globals -- no allocation allowed in kernel_launch)
// ---------------------------------------------------------------------------
__device__ float g_h[N_MAX * HDIM];     // h = A @ W
__device__ float g_agg[N_MAX * HDIM];   // scatter accumulator
__device__ float g_feat[N_MAX * HDIM];  // layer output (feat1 then feat2)
__device__ float g_inv[N_MAX];          // deg, then rsqrt(deg)

// ---------------------------------------------------------------------------
// Degree / normalization
// ---------------------------------------------------------------------------
__global__ void deg_init_kernel(float* deg, int n) {
    int i = blockIdx.x * blockDim.x + threadIdx.x;
    if (i < n) deg[i] = 1.0f;  // self loop
}

__global__ void deg_count_kernel(const int* __restrict__ dst, float* deg, int e) {
    int i = blockIdx.x * blockDim.x + threadIdx.x;
    if (i < e) atomicAdd(&deg[dst[i]], 1.0f);
}

__global__ void inv_sqrt_kernel(float* deg, int n) {
    int i = blockIdx.x * blockDim.x + threadIdx.x;
    if (i < n) deg[i] = rsqrtf(deg[i]);   // deg >= 1 always
}

// ---------------------------------------------------------------------------
// SGEMM (fp32, proven): C[M,256] = A[M,256] @ B[256,256]
// BM=128, BN=128, BK=16, 256 threads, 8x8 per thread
// ---------------------------------------------------------------------------
__global__ __launch_bounds__(256) void sgemm_kernel(
    const float* __restrict__ A, const float* __restrict__ B,
    float* __restrict__ C, int M)
{
    const int K = 256;
    __shared__ float As[16][128];   // transposed: As[k][m]
    __shared__ float Bs[16][128];

    const int block_row = blockIdx.x * 128;
    const int block_col = blockIdx.y * 128;
    const int tid = threadIdx.x;
    const int tr = tid >> 4;            // 0..15
    const int tc = tid & 15;            // 0..15

    const int a_row0 = tid >> 2;        // 0..63
    const int a_col  = (tid & 3) * 4;   // 0,4,8,12
    const int b_row0 = tid >> 5;        // 0..7
    const int b_col  = (tid & 31) * 4;  // 0..124

    float acc[8][8] = {};

    for (int k0 = 0; k0 < K; k0 += 16) {
        #pragma unroll
        for (int it = 0; it < 2; ++it) {
            int m = a_row0 + it * 64;
            int gr = block_row + m;
            float4 v = make_float4(0.f, 0.f, 0.f, 0.f);
            if (gr < M) v = *(const float4*)(A + (size_t)gr * K + k0 + a_col);
            As[a_col + 0][m] = v.x;
            As[a_col + 1][m] = v.y;
            As[a_col + 2][m] = v.z;
            As[a_col + 3][m] = v.w;
        }
        #pragma unroll
        for (int it = 0; it < 2; ++it) {
            int kk = b_row0 + it * 8;
            *(float4*)&Bs[kk][b_col] =
                *(const float4*)(B + (size_t)(k0 + kk) * 256 + block_col + b_col);
        }
        __syncthreads();

        #pragma unroll
        for (int kk = 0; kk < 16; ++kk) {
            float4 a0 = *(const float4*)&As[kk][tr * 8];
            float4 a1 = *(const float4*)&As[kk][tr * 8 + 4];
            float4 b0 = *(const float4*)&Bs[kk][tc * 8];
            float4 b1 = *(const float4*)&Bs[kk][tc * 8 + 4];
            float ar[8] = {a0.x, a0.y, a0.z, a0.w, a1.x, a1.y, a1.z, a1.w};
            float br[8] = {b0.x, b0.y, b0.z, b0.w, b1.x, b1.y, b1.z, b1.w};
            #pragma unroll
            for (int i = 0; i < 8; ++i)
                #pragma unroll
                for (int j = 0; j < 8; ++j)
                    acc[i][j] += ar[i] * br[j];
        }
        __syncthreads();
    }

    #pragma unroll
    for (int i = 0; i < 8; ++i) {
        int gr = block_row + tr * 8 + i;
        if (gr < M) {
            #pragma unroll
            for (int j = 0; j < 8; j += 4) {
                *(float4*)(C + (size_t)gr * 256 + block_col + tc * 8 + j) =
                    make_float4(acc[i][j], acc[i][j+1], acc[i][j+2], acc[i][j+3]);
            }
        }
    }
}

// ---------------------------------------------------------------------------
// Self-loop init: agg[v,:] = h[v,:] * inv[v]^2   (float4 granularity)
// ---------------------------------------------------------------------------
__global__ void selfinit_kernel(const float* __restrict__ h,
                                const float* __restrict__ inv,
                                float* __restrict__ agg, int total4)
{
    int t = blockIdx.x * blockDim.x + threadIdx.x;
    if (t >= total4) return;
    int row = t >> 6;   // 64 float4 per row
    float iv = inv[row]; iv *= iv;
    float4 v = ((const float4*)h)[t];
    v.x *= iv; v.y *= iv; v.z *= iv; v.w *= iv;
    ((float4*)agg)[t] = v;
}

// ---------------------------------------------------------------------------
// Edge scatter: agg[dst,:] += h[src,:] * inv[src]*inv[dst]
// One warp per edge, vectorized global reductions (red.global.add.v4.f32)
// ---------------------------------------------------------------------------
__global__ void scatter_kernel(const float* __restrict__ h,
                               const int* __restrict__ src,
                               const int* __restrict__ dst,
                               const float* __restrict__ inv,
                               float* __restrict__ agg, int e)
{
    int warp = (blockIdx.x * blockDim.x + threadIdx.x) >> 5;
    int lane = threadIdx.x & 31;
    if (warp >= e) return;
    int s = __ldg(&src[warp]);
    int d = __ldg(&dst[warp]);
    float coef = __ldg(&inv[s]) * __ldg(&inv[d]);
    const float4* hp = (const float4*)(h + (size_t)s * 256);
    float* ap = agg + (size_t)d * 256;
    #pragma unroll
    for (int it = 0; it < 2; ++it) {
        int idx = lane + it * 32;           // float4 index 0..63
        float4 v = hp[idx];
        v.x *= coef; v.y *= coef; v.z *= coef; v.w *= coef;
        asm volatile("red.global.add.v4.f32 [%0], {%1, %2, %3, %4};"
                     :: "l"(ap + (size_t)idx * 4),
                        "f"(v.x), "f"(v.y), "f"(v.z), "f"(v.w)
                     : "memory");
    }
}

// ---------------------------------------------------------------------------
// Epilogue: feat = (agg + b), optional relu     (float4 granularity)
// ---------------------------------------------------------------------------
template <bool RELU>
__global__ void epilogue_kernel(const float* __restrict__ agg,
                                const float* __restrict__ b,
                                float* __restrict__ feat, int total4)
{
    int t = blockIdx.x * blockDim.x + threadIdx.x;
    if (t >= total4) return;
    int c4 = t & 63;
    float4 v  = ((const float4*)agg)[t];
    float4 bb = ((const float4*)b)[c4];
    v.x += bb.x; v.y += bb.y; v.z += bb.z; v.w += bb.w;
    if (RELU) {
        v.x = fmaxf(v.x, 0.f); v.y = fmaxf(v.y, 0.f);
        v.z = fmaxf(v.z, 0.f); v.w = fmaxf(v.w, 0.f);
    }
    ((float4*)feat)[t] = v;
}

// ---------------------------------------------------------------------------
// TF32 helpers
// ---------------------------------------------------------------------------
__device__ __forceinline__ uint32_t f2tf(float x) {
    uint32_t r;
    asm("cvt.rna.tf32.f32 %0, %1;" : "=r"(r) : "f"(x));
    return r;
}

__device__ __forceinline__ void mma_tf32(float d[4], const uint32_t a[4],
                                         const uint32_t b[2]) {
    asm volatile(
        "mma.sync.aligned.m16n8k8.row.col.f32.tf32.tf32.f32 "
        "{%0,%1,%2,%3}, {%4,%5,%6,%7}, {%8,%9}, {%0,%1,%2,%3};"
        : "+f"(d[0]), "+f"(d[1]), "+f"(d[2]), "+f"(d[3])
        : "r"(a[0]), "r"(a[1]), "r"(a[2]), "r"(a[3]),
          "r"(b[0]), "r"(b[1]));
}

// ---------------------------------------------------------------------------
// Context GEMM on TF32 tensor cores, fused final product:
//   out[i,c] = feat2[i,c] * ( sum_{j<len[i]} feat2[label[i,j],:] @ Wr[j*256:, c]
//                             + rb[c] )
// Block tile 128x128, BK=32, 8 warps (2x4), warp tile 64x32 via m16n8k8.
// Register double-buffering of the global->smem staging. Per-block K skipping
// based on max context_len in the row tile.
// ---------------------------------------------------------------------------
__global__ __launch_bounds__(256, 1) void ctx_gemm_tc_kernel(
    const float* __restrict__ feat,
    const int* __restrict__ label,     // [M, 8]
    const int* __restrict__ clen,      // [M]
    const float* __restrict__ Wr,      // [2048, 256]
    const float* __restrict__ rb,      // [256]
    float* __restrict__ out, int M)
{
    __shared__ uint32_t As[32][132];    // logical A[k][m], padded
    __shared__ uint32_t Bsp[16][260];   // B k-pair interleaved: see storeTiles
    __shared__ int s_label[128][MAXCTX];
    __shared__ int s_len[128];
    __shared__ int s_maxlen;

    const int brow = blockIdx.x * 128;
    const int bcol = blockIdx.y * 128;
    const int tid  = threadIdx.x;
    const int lane = tid & 31;
    const int warp = tid >> 5;
    const int g    = lane >> 2;   // 0..7
    const int tig  = lane & 3;    // 0..3
    const int wm   = warp & 1;    // warp row (2)
    const int wn   = warp >> 1;   // warp col (4)

    // --- stage per-row metadata ---
    if (tid < 128) {
        int gr = brow + tid;
        s_len[tid] = (gr < M) ? clen[gr] : 0;
    }
    for (int i = tid; i < 128 * MAXCTX; i += 256) {
        int r = i >> 3, j = i & 7;
        int gr = brow + r;
        s_label[r][j] = (gr < M) ? label[(size_t)gr * MAXCTX + j] : 0;
    }
    __syncthreads();
    if (warp == 0) {
        int v = max(max(s_len[lane], s_len[lane + 32]),
                    max(s_len[lane + 64], s_len[lane + 96]));
        #pragma unroll
        for (int o = 16; o; o >>= 1) v = max(v, __shfl_xor_sync(0xffffffffu, v, o));
        if (lane == 0) s_maxlen = v;
    }
    __syncthreads();
    const int K_eff = s_maxlen * 256;   // skip fully-masked context slots

    float acc[4][4][4];
    #pragma unroll
    for (int i = 0; i < 4; ++i)
        #pragma unroll
        for (int j = 0; j < 4; ++j)
            #pragma unroll
            for (int c = 0; c < 4; ++c) acc[i][j][c] = 0.f;

    // loader indices
    const int lm  = tid >> 1;          // A row 0..127
    const int lkb = (tid & 1) * 16;    // A k-base 0 / 16
    const int bkk = tid & 31;          // B k-row 0..31
    const int bnb = (tid >> 5) * 16;   // B n-base

    float4 rA[4], rB[4];

    auto loadTiles = [&](int k0) {
        const int j   = k0 >> 8;            // context slot (constant in a tile)
        const int kc0 = (k0 & 255) + lkb;
        const int L   = s_len[lm];
        const float* abase = feat + (size_t)s_label[lm][j] * HDIM + kc0;
        #pragma unroll
        for (int it = 0; it < 4; ++it) {
            float4 v = make_float4(0.f, 0.f, 0.f, 0.f);
            if (j < L) v = *(const float4*)(abase + it * 4);
            rA[it] = v;
        }
        const float* bbase = Wr + (size_t)(k0 + bkk) * HDIM + bcol + bnb;
        #pragma unroll
        for (int it = 0; it < 4; ++it)
            rB[it] = *(const float4*)(bbase + it * 4);
    };

    const int bprow = (bkk >> 3) * 4 + (bkk & 3);
    const int bkh   = (bkk >> 2) & 1;

    auto storeTiles = [&]() {
        #pragma unroll
        for (int it = 0; it < 4; ++it) {
            int k = lkb + it * 4;
            As[k + 0][lm] = f2tf(rA[it].x);
            As[k + 1][lm] = f2tf(rA[it].y);
            As[k + 2][lm] = f2tf(rA[it].z);
            As[k + 3][lm] = f2tf(rA[it].w);
        }
        #pragma unroll
        for (int it = 0; it < 4; ++it) {
            int n = bnb + it * 4;
            Bsp[bprow][2 * (n + 0) + bkh] = f2tf(rB[it].x);
            Bsp[bprow][2 * (n + 1) + bkh] = f2tf(rB[it].y);
            Bsp[bprow][2 * (n + 2) + bkh] = f2tf(rB[it].z);
            Bsp[bprow][2 * (n + 3) + bkh] = f2tf(rB[it].w);
        }
    };

    if (K_eff > 0) {
        loadTiles(0);
        storeTiles();
        __syncthreads();

        for (int k0 = 0; k0 < K_eff; k0 += 32) {
            bool more = (k0 + 32) < K_eff;
            if (more) loadTiles(k0 + 32);   // overlap with compute below

            #pragma unroll
            for (int ks = 0; ks < 4; ++ks) {
                uint32_t af[4][4], bf[4][2];
                #pragma unroll
                for (int i = 0; i < 4; ++i) {
                    int mb = wm * 64 + i * 16 + g;
                    af[i][0] = As[ks * 8 + tig    ][mb];
                    af[i][1] = As[ks * 8 + tig    ][mb + 8];
                    af[i][2] = As[ks * 8 + tig + 4][mb];
                    af[i][3] = As[ks * 8 + tig + 4][mb + 8];
                }
                #pragma unroll
                for (int jn = 0; jn < 4; ++jn) {
                    int n = wn * 32 + jn * 8 + g;
                    // b0 (k=tig) and b1 (k=tig+4) are adjacent -> one LDS.64
                    uint2 bb = *(const uint2*)&Bsp[ks * 4 + tig][2 * n];
                    bf[jn][0] = bb.x;
                    bf[jn][1] = bb.y;
                }
                #pragma unroll
                for (int i = 0; i < 4; ++i)
                    #pragma unroll
                    for (int jn = 0; jn < 4; ++jn)
                        mma_tf32(acc[i][jn], af[i], bf[jn]);
            }
            __syncthreads();
            if (more) { storeTiles(); __syncthreads(); }
        }
    }

    // fused epilogue: out = feat2 * (acc + rb)
    #pragma unroll
    for (int i = 0; i < 4; ++i) {
        int r0 = brow + wm * 64 + i * 16 + g;
        int r1 = r0 + 8;
        #pragma unroll
        for (int jn = 0; jn < 4; ++jn) {
            int c = bcol + wn * 32 + jn * 8 + tig * 2;
            float2 bv = *(const float2*)(rb + c);
            if (r0 < M) {
                float2 fv = *(const float2*)(feat + (size_t)r0 * HDIM + c);
                float2 o;
                o.x = (acc[i][jn][0] + bv.x) * fv.x;
                o.y = (acc[i][jn][1] + bv.y) * fv.y;
                *(float2*)(out + (size_t)r0 * HDIM + c) = o;
            }
            if (r1 < M) {
                float2 fv = *(const float2*)(feat + (size_t)r1 * HDIM + c);
                float2 o;
                o.x = (acc[i][jn][2] + bv.x) * fv.x;
                o.y = (acc[i][jn][3] + bv.y) * fv.y;
                *(float2*)(out + (size_t)r1 * HDIM + c) = o;
            }
        }
    }
}

// ---------------------------------------------------------------------------
// Launch
// ---------------------------------------------------------------------------
extern "C" void kernel_launch(void* const* d_in, const int* in_sizes, int n_in,
                              void* d_out, int out_size)
{
    const float* x     = (const float*)d_in[0];
    const int*   ei    = (const int*)  d_in[1];   // [2, E]: src row then dst row
    const int*   label = (const int*)  d_in[2];
    const int*   clen  = (const int*)  d_in[3];
    const float* gW    = (const float*)d_in[4];
    const float* gb    = (const float*)d_in[5];
    const float* rW    = (const float*)d_in[6];
    const float* rb    = (const float*)d_in[7];
    float*       out   = (float*)d_out;

    const int N = in_sizes[3];
    const int E = in_sizes[1] / 2;
    const int* src = ei;
    const int* dst = ei + E;

    float *h, *agg, *feat, *inv;
    cudaGetSymbolAddress((void**)&h,    g_h);
    cudaGetSymbolAddress((void**)&agg,  g_agg);
    cudaGetSymbolAddress((void**)&feat, g_feat);
    cudaGetSymbolAddress((void**)&inv,  g_inv);

    const int total4 = N * (HDIM / 4);           // float4 count of a feature buf
    const int TPB = 256;
    dim3 gemm_grid((N + 127) / 128, 2);

    // --- normalization ---
    deg_init_kernel<<<(N + TPB - 1) / TPB, TPB>>>(inv, N);
    deg_count_kernel<<<(E + TPB - 1) / TPB, TPB>>>(dst, inv, E);
    inv_sqrt_kernel<<<(N + TPB - 1) / TPB, TPB>>>(inv, N);

    // --- GCN layer 1: feat1 = relu(scatter(x@W) + b) ---
    sgemm_kernel<<<gemm_grid, TPB>>>(x, gW, h, N);
    selfinit_kernel<<<(total4 + TPB - 1) / TPB, TPB>>>(h, inv, agg, total4);
    scatter_kernel<<<(E * 32 + TPB - 1) / TPB, TPB>>>(h, src, dst, inv, agg, E);
    epilogue_kernel<true><<<(total4 + TPB - 1) / TPB, TPB>>>(agg, gb, feat, total4);

    // --- GCN layer 2: feat2 = scatter(feat1@W) + b ---
    sgemm_kernel<<<gemm_grid, TPB>>>(feat, gW, h, N);
    selfinit_kernel<<<(total4 + TPB - 1) / TPB, TPB>>>(h, inv, agg, total4);
    scatter_kernel<<<(E * 32 + TPB - 1) / TPB, TPB>>>(h, src, dst, inv, agg, E);
    epilogue_kernel<false><<<(total4 + TPB - 1) / TPB, TPB>>>(agg, gb, feat, total4);

    // --- context gather-GEMM on TF32 tensor cores, fused final product ---
    ctx_gemm_tc_kernel<<<gemm_grid, TPB>>>(feat, label, clen, rW, rb, out, N);
}